// round 4
// baseline (speedup 1.0000x reference)
#include <cuda_runtime.h>
#include <cuda_bf16.h>

// MoebiusTransformer: BATCH rows (8192 nominal), 512 independent 3-D moebius
// maps per row (N_FEATURES=1536, DIM=3). Analytic closed-form 3x3 log|det|
// (matrix-determinant lemma) replaces slogdet.
// Memory-bound: ~151 MB traffic -> ~24us floor on GB300.

#define MB_NF    1536
#define MB_NV    512          // MB_NF / 3
#define MB_MAXR  0.99f

__global__ __launch_bounds__(512) void moebius_kernel(
    const float* __restrict__ x,
    const float* __restrict__ w,
    float* __restrict__ out,   // [BATCH*NF] y, then [BATCH] log_det_J
    int batch)
{
    __shared__ float sx[MB_NF];
    __shared__ float sw[MB_NF];   // reused for y after compute
    __shared__ float red[16];

    const int b = blockIdx.x;
    const int t = threadIdx.x;

    // ---- stage x, w tiles with float4 loads (coalesced 128B lines) ----
    const float4* x4 = reinterpret_cast<const float4*>(x + (size_t)b * MB_NF);
    const float4* w4 = reinterpret_cast<const float4*>(w + (size_t)b * MB_NF);
    if (t < MB_NF / 4) {
        reinterpret_cast<float4*>(sx)[t] = x4[t];
        reinterpret_cast<float4*>(sw)[t] = w4[t];
    }
    __syncthreads();

    // ---- per-thread 3-vector (stride-3 smem reads: conflict-free, gcd(3,32)=1) ----
    const float X0 = sx[3 * t + 0], X1 = sx[3 * t + 1], X2 = sx[3 * t + 2];
    const float W0 = sw[3 * t + 0], W1 = sw[3 * t + 1], W2 = sw[3 * t + 2];

    const float wn2 = fmaf(W0, W0, fmaf(W1, W1, W2 * W2));
    const float xn2 = fmaf(X0, X0, fmaf(X1, X1, X2 * X2));
    const float wn  = sqrtf(wn2);
    const float xn  = sqrtf(xn2);

    // rescaling r = 0.99 * xn / (1 + wn)
    const float r = (MB_MAXR * xn) / (1.0f + wn);
    const float ws0 = r * W0, ws1 = r * W1, ws2 = r * W2;
    const float wns = r * wn;

    const float num = fmaf(-wns, wns, xn2);          // xn^2 - wns^2
    const float d0 = X0 - ws0, d1 = X1 - ws1, d2 = X2 - ws2;
    const float dn2 = fmaf(d0, d0, fmaf(d1, d1, d2 * d2));
    const float inv_dn2 = 1.0f / dn2;
    const float a = num * inv_dn2;

    // y = a*d - ws
    const float y0 = fmaf(a, d0, -ws0);
    const float y1 = fmaf(a, d1, -ws1);
    const float y2 = fmaf(a, d2, -ws2);

    // ---- analytic det(J); J = a*I + b*d d^T + u x^T, b = -2a/dn2, u = v/xn2 ----
    const float dx = fmaf(d0, X0, fmaf(d1, X1, d2 * X2));
    const float c  = -2.0f * a * inv_dn2 * dx;       // b * (d.x)
    const float v0 = y0 - fmaf(a, X0, c * d0);
    const float v1 = y1 - fmaf(a, X1, c * d1);
    const float v2 = y2 - fmaf(a, X2, c * d2);
    const float xv = fmaf(X0, v0, fmaf(X1, v1, X2 * v2));
    const float dv = fmaf(d0, v0, fmaf(d1, v1, d2 * v2));
    const float inv_xn2 = 1.0f / xn2;
    // s = (x.v - 2/dn2 * (d.x)(d.v)) / xn2 ;  detJ = -a^2 (a + s)
    const float s = inv_xn2 * fmaf(-2.0f * inv_dn2 * dx, dv, xv);
    const float detJ = -a * a * (a + s);

    // accurate log path: the row-sum of 512 signed logs can cancel, so keep
    // per-term error ~1 ulp (we have >2x compute headroom vs the HBM floor)
    float ld = logf(fabsf(detJ));

    // ---- write y into dead w-smem (each thread touches only its own slots) ----
    sw[3 * t + 0] = y0;
    sw[3 * t + 1] = y1;
    sw[3 * t + 2] = y2;

    // ---- reduce log|det| over the 512 vectors of this row ----
    #pragma unroll
    for (int o = 16; o > 0; o >>= 1)
        ld += __shfl_xor_sync(0xffffffffu, ld, o);
    if ((t & 31) == 0) red[t >> 5] = ld;
    __syncthreads();

    // ---- float4 store of y ----
    float4* yo = reinterpret_cast<float4*>(out + (size_t)b * MB_NF);
    if (t < MB_NF / 4)
        yo[t] = reinterpret_cast<const float4*>(sw)[t];

    if (t == 0) {
        float tot = 0.0f;
        #pragma unroll
        for (int i = 0; i < 16; i++) tot += red[i];
        out[(size_t)batch * MB_NF + b] = tot;
    }
}

extern "C" void kernel_launch(void* const* d_in, const int* in_sizes, int n_in,
                              void* d_out, int out_size) {
    const float* x = (const float*)d_in[0];
    const float* w = (const float*)d_in[1];
    float* out = (float*)d_out;
    const int batch = in_sizes[0] / MB_NF;   // robust to batch-shape variants
    moebius_kernel<<<batch, 512>>>(x, w, out, batch);
}

// round 16
// speedup vs baseline: 1.2363x; 1.2363x over previous
#include <cuda_runtime.h>
#include <cuda_bf16.h>

// MoebiusTransformer: BATCH rows (8192 nominal), 512 independent 3-D moebius
// maps per row (N_FEATURES=1536, DIM=3). Analytic closed-form 3x3 log|det|
// (matrix-determinant lemma) replaces slogdet.
// R4: issue/latency-bound per ncu (all pipes <40%, occ 65.7% reg-capped at
// 3 CTAs/SM). Force 4 CTAs/SM + MUFU-approx transcendentals.

#define MB_NF    1536
#define MB_NV    512          // MB_NF / 3
#define MB_MAXR  0.99f

__device__ __forceinline__ float frcp_ap(float a) {
    float r; asm("rcp.approx.f32 %0, %1;" : "=f"(r) : "f"(a)); return r;
}
__device__ __forceinline__ float fsqrt_ap(float a) {
    float r; asm("sqrt.approx.f32 %0, %1;" : "=f"(r) : "f"(a)); return r;
}

__global__ __launch_bounds__(512, 4) void moebius_kernel(
    const float* __restrict__ x,
    const float* __restrict__ w,
    float* __restrict__ out,   // [BATCH*NF] y, then [BATCH] log_det_J
    int batch)
{
    __shared__ float sx[MB_NF];
    __shared__ float sw[MB_NF];   // reused for y after compute
    __shared__ float red[16];

    const int b = blockIdx.x;
    const int t = threadIdx.x;

    // ---- stage x, w tiles with float4 loads (coalesced 128B lines) ----
    const float4* x4 = reinterpret_cast<const float4*>(x + (size_t)b * MB_NF);
    const float4* w4 = reinterpret_cast<const float4*>(w + (size_t)b * MB_NF);
    if (t < MB_NF / 4) {
        reinterpret_cast<float4*>(sx)[t] = x4[t];
        reinterpret_cast<float4*>(sw)[t] = w4[t];
    }
    __syncthreads();

    // ---- per-thread 3-vector (stride-3 smem reads: conflict-free, gcd(3,32)=1) ----
    const float X0 = sx[3 * t + 0], X1 = sx[3 * t + 1], X2 = sx[3 * t + 2];
    const float W0 = sw[3 * t + 0], W1 = sw[3 * t + 1], W2 = sw[3 * t + 2];

    const float wn2 = fmaf(W0, W0, fmaf(W1, W1, W2 * W2));
    const float xn2 = fmaf(X0, X0, fmaf(X1, X1, X2 * X2));
    const float wn  = fsqrt_ap(wn2);
    const float xn  = fsqrt_ap(xn2);

    // rescaling r = 0.99 * xn / (1 + wn)
    const float r = (MB_MAXR * xn) * frcp_ap(1.0f + wn);
    const float ws0 = r * W0, ws1 = r * W1, ws2 = r * W2;
    const float wns = r * wn;

    const float num = fmaf(-wns, wns, xn2);          // xn^2 - wns^2
    const float d0 = X0 - ws0, d1 = X1 - ws1, d2 = X2 - ws2;
    const float dn2 = fmaf(d0, d0, fmaf(d1, d1, d2 * d2));
    const float inv_dn2 = frcp_ap(dn2);
    const float a = num * inv_dn2;

    // y = a*d - ws
    const float y0 = fmaf(a, d0, -ws0);
    const float y1 = fmaf(a, d1, -ws1);
    const float y2 = fmaf(a, d2, -ws2);

    // ---- analytic det(J); J = a*I + b*d d^T + u x^T, b = -2a/dn2, u = v/xn2 ----
    const float dx = fmaf(d0, X0, fmaf(d1, X1, d2 * X2));
    const float c  = -2.0f * a * inv_dn2 * dx;       // b * (d.x)
    const float v0 = y0 - fmaf(a, X0, c * d0);
    const float v1 = y1 - fmaf(a, X1, c * d1);
    const float v2 = y2 - fmaf(a, X2, c * d2);
    const float xv = fmaf(X0, v0, fmaf(X1, v1, X2 * v2));
    const float dv = fmaf(d0, v0, fmaf(d1, v1, d2 * v2));
    const float inv_xn2 = frcp_ap(xn2);
    // s = (x.v - 2/dn2 * (d.x)(d.v)) / xn2 ;  detJ = -a^2 (a + s)
    const float s = inv_xn2 * fmaf(-2.0f * inv_dn2 * dx, dv, xv);
    const float detJ = -a * a * (a + s);

    // fast log: rel_err budget is 1e-3, measured 1.3e-7 with accurate logf —
    // MUFU.LG2 path keeps ~1e-6..1e-5, 100x margin, and cuts regs + fma work
    float ld = __logf(fabsf(detJ));

    // ---- write y into dead w-smem (each thread touches only its own slots) ----
    sw[3 * t + 0] = y0;
    sw[3 * t + 1] = y1;
    sw[3 * t + 2] = y2;

    // ---- reduce log|det| over the 512 vectors of this row ----
    #pragma unroll
    for (int o = 16; o > 0; o >>= 1)
        ld += __shfl_xor_sync(0xffffffffu, ld, o);
    if ((t & 31) == 0) red[t >> 5] = ld;
    __syncthreads();

    // ---- float4 store of y ----
    float4* yo = reinterpret_cast<float4*>(out + (size_t)b * MB_NF);
    if (t < MB_NF / 4)
        yo[t] = reinterpret_cast<const float4*>(sw)[t];

    if (t == 0) {
        float tot = 0.0f;
        #pragma unroll
        for (int i = 0; i < 16; i++) tot += red[i];
        out[(size_t)batch * MB_NF + b] = tot;
    }
}

extern "C" void kernel_launch(void* const* d_in, const int* in_sizes, int n_in,
                              void* d_out, int out_size) {
    const float* x = (const float*)d_in[0];
    const float* w = (const float*)d_in[1];
    float* out = (float*)d_out;
    const int batch = in_sizes[0] / MB_NF;   // robust to batch-shape variants
    moebius_kernel<<<batch, 512>>>(x, w, out, batch);
}